// round 12
// baseline (speedup 1.0000x reference)
#include <cuda_runtime.h>
#include <cuda_fp16.h>
#include <cstdint>

#define DB 4
#define DT 256
#define DU 64
#define DENC 512
#define DPRED 640
#define DJ 640
#define DV 1024
#define BT (DB*DT)        // 1024 enc rows
#define BUROWS (DB*DU)    // 256 pred rows
#define M_TOTAL (BT*DU)   // 65536 joint rows

// ---------------- device scratch (no allocations allowed) ----------------
__device__ float  g_encP[BT * DJ];                 // 2.6 MB
__device__ float  g_predP[BUROWS * DJ];            // 0.66 MB
__device__ __half g_joint[(size_t)M_TOTAL * DJ];   // 84 MB
__device__ __half g_Wh[DV * DJ];                   // W_out^T [v][k]
__device__ __half g_encH[BT * DENC];               // enc fp16 [m][k]
__device__ __half g_predH[BUROWS * DPRED];         // pred fp16 [m][k]
__device__ __half g_WeH[DJ * DENC];                // W_enc^T fp16 [j][k]
__device__ __half g_WpH[DJ * DPRED];               // W_pred^T fp16 [j][k]

// ---------------- tanh via MUFU.TANH --------------------------------------
__device__ __forceinline__ float tanha(float x) {
    float y;
    asm("tanh.approx.f32 %0, %1;" : "=f"(y) : "f"(x));
    return y;
}

// ---------------- convert: enc/pred fp32->fp16, W_enc/W_pred transpose ----
__global__ void __launch_bounds__(256) convert_kernel(const float* __restrict__ enc,
                                                      const float* __restrict__ pred,
                                                      const float* __restrict__ W_enc,
                                                      const float* __restrict__ W_pred) {
    const int bx = blockIdx.x, tid = threadIdx.x;
    if (bx < 64) {                       // enc: 131072 float4
        const float4* src = (const float4*)enc;
        for (int i = bx * 256 + tid; i < (BT * DENC) / 4; i += 64 * 256) {
            float4 v = src[i];
            __half2 h0 = __floats2half2_rn(v.x, v.y);
            __half2 h1 = __floats2half2_rn(v.z, v.w);
            int2 o; o.x = *(int*)&h0; o.y = *(int*)&h1;
            ((int2*)g_encH)[i] = o;
        }
    } else if (bx < 80) {                // pred: 40960 float4
        const float4* src = (const float4*)pred;
        for (int i = (bx - 64) * 256 + tid; i < (BUROWS * DPRED) / 4; i += 16 * 256) {
            float4 v = src[i];
            __half2 h0 = __floats2half2_rn(v.x, v.y);
            __half2 h1 = __floats2half2_rn(v.z, v.w);
            int2 o; o.x = *(int*)&h0; o.y = *(int*)&h1;
            ((int2*)g_predH)[i] = o;
        }
    } else if (bx < 144) {               // W_enc^T: 512x640
        for (int idx = (bx - 80) * 256 + tid; idx < DENC * DJ; idx += 64 * 256) {
            int k = idx / DJ, j = idx - k * DJ;
            g_WeH[(size_t)j * DENC + k] = __float2half_rn(W_enc[idx]);
        }
    } else {                             // W_pred^T: 640x640
        for (int idx = (bx - 144) * 256 + tid; idx < DPRED * DJ; idx += 80 * 256) {
            int k = idx / DJ, j = idx - k * DJ;
            g_WpH[(size_t)j * DPRED + k] = __float2half_rn(W_pred[idx]);
        }
    }
}

// ---------------- shared GEMM helpers --------------------------------------
__device__ __forceinline__ uint32_t smem_u32(const void* p) {
    uint32_t a;
    asm("{ .reg .u64 t; cvta.to.shared.u64 t, %1; cvt.u32.u64 %0, t; }" : "=r"(a) : "l"(p));
    return a;
}
__device__ __forceinline__ uint32_t swz(uint32_t o) { return o ^ ((o >> 3) & 0x70); }
__device__ __forceinline__ void cp16(uint32_t dst, const void* src) {
    asm volatile("cp.async.cg.shared.global [%0], [%1], 16;" :: "r"(dst), "l"(src));
}
__device__ __forceinline__ void ldsm4(uint32_t& r0, uint32_t& r1, uint32_t& r2,
                                      uint32_t& r3, uint32_t a) {
    asm volatile("ldmatrix.sync.aligned.m8n8.x4.shared.b16 {%0,%1,%2,%3}, [%4];"
                 : "=r"(r0), "=r"(r1), "=r"(r2), "=r"(r3) : "r"(a));
}
__device__ __forceinline__ void mma16816(float c[4], const uint32_t a[4], const uint32_t b[2]) {
    asm volatile(
        "mma.sync.aligned.m16n8k16.row.col.f32.f16.f16.f32 "
        "{%0,%1,%2,%3}, {%4,%5,%6,%7}, {%8,%9}, {%0,%1,%2,%3};\n"
        : "+f"(c[0]), "+f"(c[1]), "+f"(c[2]), "+f"(c[3])
        : "r"(a[0]), "r"(a[1]), "r"(a[2]), "r"(a[3]), "r"(b[0]), "r"(b[1]));
}

// ---------------- proj via tensor cores (+ W_out convert blocks) -----------
// blocks [0,160): encP; [160,200): predP; [200,264): W_out^T fp16 convert.
#define PROJ_SMEM (3 * 16384)
__global__ void __launch_bounds__(128) proj_mma(const float* __restrict__ b_enc,
                                                const float* __restrict__ b_pred,
                                                const float* __restrict__ W_out) {
    extern __shared__ char ds[];
    const int bx = blockIdx.x;
    if (bx >= 200) {                     // W_out^T: 640x1024 -> g_Wh [v][k]
        for (int idx = (bx - 200) * 128 + threadIdx.x; idx < DJ * DV; idx += 64 * 128) {
            int k = idx >> 10, v = idx & 1023;
            g_Wh[(size_t)v * DJ + k] = __float2half_rn(W_out[idx]);
        }
        return;
    }
    const uint32_t sbase = smem_u32(ds);
    const int tid  = threadIdx.x;
    const int warp = tid >> 5;
    const int lane = tid & 31;
    const int g = lane >> 2;
    const int t = lane & 3;
    const int wm = (warp >> 1) * 32;
    const int wn = (warp & 1) * 32;

    const __half *Asrc, *Bsrc;
    const float* bias;
    float* dst;
    int m0, n0, K, ktiles;
    if (bx < 160) {
        m0 = (bx / 10) * 64; n0 = (bx % 10) * 64;
        K = DENC; ktiles = 8;
        Asrc = g_encH; Bsrc = g_WeH; bias = b_enc; dst = g_encP;
    } else {
        int bb = bx - 160;
        m0 = (bb / 10) * 64; n0 = (bb % 10) * 64;
        K = DPRED; ktiles = 10;
        Asrc = g_predH; Bsrc = g_WpH; bias = b_pred; dst = g_predP;
    }

    auto load_stage = [&](int s, int kt) {
        const uint32_t stA = sbase + s * 16384;
        const uint32_t stB = stA + 8192;
        const int koff = kt * 64;
#pragma unroll
        for (int q = 0; q < 4; q++) {
            int id = tid + 128 * q;
            int row = id >> 3, c16 = id & 7;
            cp16(stA + swz(row * 128 + c16 * 16), Asrc + (size_t)(m0 + row) * K + koff + c16 * 8);
        }
#pragma unroll
        for (int q = 0; q < 4; q++) {
            int id = tid + 128 * q;
            int row = id >> 3, c16 = id & 7;
            cp16(stB + swz(row * 128 + c16 * 16), Bsrc + (size_t)(n0 + row) * K + koff + c16 * 8);
        }
        asm volatile("cp.async.commit_group;" ::: "memory");
    };

    const int rowA  = wm + (lane & 15);
    const uint32_t kbA  = (lane >> 4) * 16;
    const uint32_t xorA = (uint32_t)(rowA & 7) * 16;
    const int rowB  = wn + (lane & 7) + ((lane >> 4) << 3);
    const uint32_t kbB  = ((lane >> 3) & 1) * 16;
    const uint32_t xorB = (uint32_t)(lane & 7) * 16;

    float acc[2][4][4];
#pragma unroll
    for (int i = 0; i < 2; i++)
#pragma unroll
        for (int j = 0; j < 4; j++)
#pragma unroll
            for (int q = 0; q < 4; q++) acc[i][j][q] = 0.0f;

    auto compute = [&](int s) {
        const uint32_t stA = sbase + s * 16384;
        const uint32_t stB = stA + 8192;
#pragma unroll
        for (int ks = 0; ks < 4; ks++) {
            const uint32_t kb = ks * 32;
            uint32_t a[2][4];
#pragma unroll
            for (int i = 0; i < 2; i++)
                ldsm4(a[i][0], a[i][1], a[i][2], a[i][3],
                      stA + (uint32_t)(rowA + i * 16) * 128 + ((kb + kbA) ^ xorA));
            uint32_t b[4][2];
#pragma unroll
            for (int jp = 0; jp < 2; jp++) {
                uint32_t r0, r1, r2, r3;
                ldsm4(r0, r1, r2, r3,
                      stB + (uint32_t)(rowB + jp * 16) * 128 + ((kb + kbB) ^ xorB));
                b[2*jp][0] = r0; b[2*jp][1] = r1;
                b[2*jp+1][0] = r2; b[2*jp+1][1] = r3;
            }
#pragma unroll
            for (int i = 0; i < 2; i++)
#pragma unroll
                for (int j = 0; j < 4; j++)
                    mma16816(acc[i][j], a[i], b[j]);
        }
    };

    load_stage(0, 0);
    load_stage(1, 1);
#pragma unroll 1
    for (int kt = 0; kt < ktiles; kt++) {
        asm volatile("cp.async.wait_group 1;" ::: "memory");
        __syncthreads();
        if (kt + 2 < ktiles) load_stage((kt + 2) % 3, kt + 2);
        else asm volatile("cp.async.commit_group;" ::: "memory");
        compute(kt % 3);
    }

#pragma unroll
    for (int j = 0; j < 4; j++) {
        int col = n0 + wn + j * 8 + 2 * t;
        float bo0 = __ldg(bias + col), bo1 = __ldg(bias + col + 1);
#pragma unroll
        for (int i = 0; i < 2; i++) {
            int r0 = m0 + wm + i * 16 + g;
            float2 v0, v1;
            v0.x = acc[i][j][0] + bo0; v0.y = acc[i][j][1] + bo1;
            v1.x = acc[i][j][2] + bo0; v1.y = acc[i][j][3] + bo1;
            *(float2*)(dst + (size_t)r0 * DJ + col)       = v0;
            *(float2*)(dst + (size_t)(r0 + 8) * DJ + col) = v1;
        }
    }
}

// ---------------- joint = tanh(encP + predP) -> fp16 ----------------------
// Divisionless 2-D mapping: block (80 chunks, 8 u-rows), grid (1024 bt, 8).
// All 8 y-threads of a (tx) column read the SAME enc chunk (L1 broadcast).
__global__ void __launch_bounds__(640) joint_tanh_kernel() {
    const int ch = threadIdx.x;                  // 0..79 (int4 chunk)
    const int u  = blockIdx.y * 8 + threadIdx.y; // 0..63
    const int bt = blockIdx.x;                   // 0..1023
    const int b  = bt >> 8;
    const float4* e = (const float4*)(g_encP  + (size_t)bt * DJ + ch * 8);
    const float4* p = (const float4*)(g_predP + (size_t)(b * DU + u) * DJ + ch * 8);
    float4 e0 = e[0], e1 = e[1];
    float4 p0 = p[0], p1 = p[1];
    __half2 q0 = __floats2half2_rn(tanha(e0.x + p0.x), tanha(e0.y + p0.y));
    __half2 q1 = __floats2half2_rn(tanha(e0.z + p0.z), tanha(e0.w + p0.w));
    __half2 q2 = __floats2half2_rn(tanha(e1.x + p1.x), tanha(e1.y + p1.y));
    __half2 q3 = __floats2half2_rn(tanha(e1.z + p1.z), tanha(e1.w + p1.w));
    int4 v;
    v.x = *(int*)&q0; v.y = *(int*)&q1; v.z = *(int*)&q2; v.w = *(int*)&q3;
    *(int4*)(g_joint + ((size_t)bt * DU + u) * DJ + ch * 8) = v;
}

// ==================== main GEMM (R11 verbatim: at mma.sync ceiling) =======
#define BM 128
#define BN 128
#define BK 64
#define KTILES 10
#define ASZ (BM*BK*2)
#define BSZ (BN*BK*2)
#define STG (ASZ+BSZ)
#define STAGES 3
#define DYN_SMEM (STAGES*STG)

__global__ void __launch_bounds__(256, 2) gemm_lm(const float* __restrict__ b_out,
                                                  float* __restrict__ out) {
    extern __shared__ char ds[];
    const uint32_t sbase = smem_u32(ds);
    const int tid  = threadIdx.x;
    const int warp = tid >> 5;
    const int lane = tid & 31;
    const int g = lane >> 2;
    const int t = lane & 3;
    const int wm = (warp >> 2) * 64;
    const int wn = (warp & 3) * 32;
    const int m0 = blockIdx.y * BM;
    const int n0 = blockIdx.x * BN;

    const __half* aG = g_joint + (size_t)m0 * DJ;
    const __half* bG = g_Wh    + (size_t)n0 * DJ;

    auto load_stage = [&](int s, int kt) {
        const uint32_t stA = sbase + s * STG;
        const uint32_t stB = stA + ASZ;
        const int koff = kt * BK;
#pragma unroll
        for (int q = 0; q < 4; q++) {
            int id = tid + 256 * q;
            int row = id >> 3, c = id & 7;
            cp16(stA + swz(row * 128 + c * 16), aG + (size_t)row * DJ + koff + c * 8);
        }
#pragma unroll
        for (int q = 0; q < 4; q++) {
            int id = tid + 256 * q;
            int row = id >> 3, c = id & 7;
            cp16(stB + swz(row * 128 + c * 16), bG + (size_t)row * DJ + koff + c * 8);
        }
        asm volatile("cp.async.commit_group;" ::: "memory");
    };

    const int rowA  = wm + (lane & 15);
    const uint32_t kbA  = (lane >> 4) * 16;
    const uint32_t xorA = (uint32_t)(rowA & 7) * 16;
    const int rowB  = wn + (lane & 7) + ((lane >> 4) << 3);
    const uint32_t kbB  = ((lane >> 3) & 1) * 16;
    const uint32_t xorB = (uint32_t)(lane & 7) * 16;

    float acc[4][4][4];
#pragma unroll
    for (int i = 0; i < 4; i++)
#pragma unroll
        for (int j = 0; j < 4; j++)
#pragma unroll
            for (int q = 0; q < 4; q++) acc[i][j][q] = 0.0f;

    auto compute = [&](int s) {
        const uint32_t stA = sbase + s * STG;
        const uint32_t stB = stA + ASZ;
#pragma unroll
        for (int ks = 0; ks < 4; ks++) {
            const uint32_t kb = ks * 32;
            uint32_t a[4][4];
#pragma unroll
            for (int i = 0; i < 4; i++)
                ldsm4(a[i][0], a[i][1], a[i][2], a[i][3],
                      stA + (uint32_t)(rowA + i * 16) * 128 + ((kb + kbA) ^ xorA));
            uint32_t b[4][2];
#pragma unroll
            for (int jp = 0; jp < 2; jp++) {
                uint32_t r0, r1, r2, r3;
                ldsm4(r0, r1, r2, r3,
                      stB + (uint32_t)(rowB + jp * 16) * 128 + ((kb + kbB) ^ xorB));
                b[2*jp][0] = r0; b[2*jp][1] = r1;
                b[2*jp+1][0] = r2; b[2*jp+1][1] = r3;
            }
#pragma unroll
            for (int i = 0; i < 4; i++)
#pragma unroll
                for (int j = 0; j < 4; j++)
                    mma16816(acc[i][j], a[i], b[j]);
        }
    };

    load_stage(0, 0);
    load_stage(1, 1);
#pragma unroll 1
    for (int kt = 0; kt < KTILES; kt++) {
        asm volatile("cp.async.wait_group 1;" ::: "memory");
        __syncthreads();
        if (kt + 2 < KTILES) load_stage((kt + 2) % 3, kt + 2);
        else asm volatile("cp.async.commit_group;" ::: "memory");
        compute(kt % 3);
    }

#pragma unroll
    for (int j = 0; j < 4; j++) {
        int col = n0 + wn + j * 8 + 2 * t;
        float bo0 = __ldg(b_out + col), bo1 = __ldg(b_out + col + 1);
#pragma unroll
        for (int i = 0; i < 4; i++) {
            int r0 = m0 + wm + i * 16 + g;
            float2 v0, v1;
            v0.x = fminf(fmaxf(acc[i][j][0] + bo0, -15.0f), 15.0f);
            v0.y = fminf(fmaxf(acc[i][j][1] + bo1, -15.0f), 15.0f);
            v1.x = fminf(fmaxf(acc[i][j][2] + bo0, -15.0f), 15.0f);
            v1.y = fminf(fmaxf(acc[i][j][3] + bo1, -15.0f), 15.0f);
            *(float2*)(out + (size_t)r0 * DV + col)       = v0;
            *(float2*)(out + (size_t)(r0 + 8) * DV + col) = v1;
        }
    }
}

// ---------------- launch ---------------------------------------------------
extern "C" void kernel_launch(void* const* d_in, const int* in_sizes, int n_in,
                              void* d_out, int out_size) {
    const float* enc    = (const float*)d_in[0];
    const float* pred   = (const float*)d_in[1];
    const float* W_enc  = (const float*)d_in[2];
    const float* b_enc  = (const float*)d_in[3];
    const float* W_pred = (const float*)d_in[4];
    const float* b_pred = (const float*)d_in[5];
    const float* W_out  = (const float*)d_in[6];
    const float* b_out  = (const float*)d_in[7];
    float* out = (float*)d_out;

    cudaFuncSetAttribute(gemm_lm, cudaFuncAttributeMaxDynamicSharedMemorySize, DYN_SMEM);
    cudaFuncSetAttribute(proj_mma, cudaFuncAttributeMaxDynamicSharedMemorySize, PROJ_SMEM);

    convert_kernel<<<224, 256>>>(enc, pred, W_enc, W_pred);
    proj_mma<<<264, 128, PROJ_SMEM>>>(b_enc, b_pred, W_out);
    joint_tanh_kernel<<<dim3(BT, 8), dim3(80, 8)>>>();
    gemm_lm<<<dim3(DV / BN, M_TOTAL / BM), 256, DYN_SMEM>>>(b_out, out);
}

// round 14
// speedup vs baseline: 1.0933x; 1.0933x over previous
#include <cuda_runtime.h>
#include <cuda_fp16.h>
#include <cstdint>

#define DB 4
#define DT 256
#define DU 64
#define DENC 512
#define DPRED 640
#define DJ 640
#define DV 1024
#define BT (DB*DT)        // 1024 enc rows
#define BUROWS (DB*DU)    // 256 pred rows
#define M_TOTAL (BT*DU)   // 65536 joint rows

// ---------------- device scratch (no allocations allowed) ----------------
__device__ float  g_encP[BT * DJ];
__device__ float  g_predP[BUROWS * DJ];
__device__ __half g_joint[(size_t)M_TOTAL * DJ];   // 84 MB
__device__ __half g_Wh[DV * DJ];                   // W_out^T [v][k]
__device__ __half g_encH[BT * DENC];
__device__ __half g_predH[BUROWS * DPRED];
__device__ __half g_WeH[DJ * DENC];                // W_enc^T [j][k]
__device__ __half g_WpH[DJ * DPRED];               // W_pred^T [j][k]

// ---------------- tanh via MUFU.TANH --------------------------------------
__device__ __forceinline__ float tanha(float x) {
    float y;
    asm("tanh.approx.f32 %0, %1;" : "=f"(y) : "f"(x));
    return y;
}

// ---------------- tiled fp32->fp16 transpose (coalesced both ways) -------
// src[K][J] fp32 -> dst[J][K] fp16, one 32x32 tile per call, 256 threads.
__device__ __forceinline__ void transpose_tile(const float* __restrict__ src,
                                               __half* __restrict__ dst,
                                               int K, int J, int tile_idx,
                                               float (*s)[33]) {
    const int tpr = J >> 5;                 // tiles per k-row
    const int tk = tile_idx / tpr;
    const int tj = tile_idx - tk * tpr;
    const int k0 = tk * 32, j0 = tj * 32;
    const int tx = threadIdx.x & 31, ty = threadIdx.x >> 5;
#pragma unroll
    for (int r = ty; r < 32; r += 8)
        s[r][tx] = src[(size_t)(k0 + r) * J + j0 + tx];
    __syncthreads();
#pragma unroll
    for (int r = ty; r < 32; r += 8)
        dst[(size_t)(j0 + r) * K + k0 + tx] = __float2half_rn(s[tx][r]);
    __syncthreads();
}

// ---------------- convert: enc/pred fp16 + W_enc/W_pred tiled transpose ---
// blocks [0,64): enc; [64,80): pred; [80,160): W_enc^T; [160,260): W_pred^T
__global__ void __launch_bounds__(256) convert_kernel(const float* __restrict__ enc,
                                                      const float* __restrict__ pred,
                                                      const float* __restrict__ W_enc,
                                                      const float* __restrict__ W_pred) {
    __shared__ float s[32][33];
    const int bx = blockIdx.x, tid = threadIdx.x;
    if (bx < 64) {
        const float4* src = (const float4*)enc;
        for (int i = bx * 256 + tid; i < (BT * DENC) / 4; i += 64 * 256) {
            float4 v = src[i];
            __half2 h0 = __floats2half2_rn(v.x, v.y);
            __half2 h1 = __floats2half2_rn(v.z, v.w);
            int2 o; o.x = *(int*)&h0; o.y = *(int*)&h1;
            ((int2*)g_encH)[i] = o;
        }
    } else if (bx < 80) {
        const float4* src = (const float4*)pred;
        for (int i = (bx - 64) * 256 + tid; i < (BUROWS * DPRED) / 4; i += 16 * 256) {
            float4 v = src[i];
            __half2 h0 = __floats2half2_rn(v.x, v.y);
            __half2 h1 = __floats2half2_rn(v.z, v.w);
            int2 o; o.x = *(int*)&h0; o.y = *(int*)&h1;
            ((int2*)g_predH)[i] = o;
        }
    } else if (bx < 160) {               // W_enc: 512x640 -> 320 tiles, 4/block
#pragma unroll
        for (int q = 0; q < 4; q++)
            transpose_tile(W_enc, g_WeH, DENC, DJ, (bx - 80) * 4 + q, s);
    } else {                             // W_pred: 640x640 -> 400 tiles, 4/block
#pragma unroll
        for (int q = 0; q < 4; q++)
            transpose_tile(W_pred, g_WpH, DPRED, DJ, (bx - 160) * 4 + q, s);
    }
}

// ---------------- shared GEMM helpers --------------------------------------
__device__ __forceinline__ uint32_t smem_u32(const void* p) {
    uint32_t a;
    asm("{ .reg .u64 t; cvta.to.shared.u64 t, %1; cvt.u32.u64 %0, t; }" : "=r"(a) : "l"(p));
    return a;
}
__device__ __forceinline__ uint32_t swz(uint32_t o) { return o ^ ((o >> 3) & 0x70); }
__device__ __forceinline__ void cp16(uint32_t dst, const void* src) {
    asm volatile("cp.async.cg.shared.global [%0], [%1], 16;" :: "r"(dst), "l"(src));
}
__device__ __forceinline__ void ldsm4(uint32_t& r0, uint32_t& r1, uint32_t& r2,
                                      uint32_t& r3, uint32_t a) {
    asm volatile("ldmatrix.sync.aligned.m8n8.x4.shared.b16 {%0,%1,%2,%3}, [%4];"
                 : "=r"(r0), "=r"(r1), "=r"(r2), "=r"(r3) : "r"(a));
}
__device__ __forceinline__ void mma16816(float c[4], const uint32_t a[4], const uint32_t b[2]) {
    asm volatile(
        "mma.sync.aligned.m16n8k16.row.col.f32.f16.f16.f32 "
        "{%0,%1,%2,%3}, {%4,%5,%6,%7}, {%8,%9}, {%0,%1,%2,%3};\n"
        : "+f"(c[0]), "+f"(c[1]), "+f"(c[2]), "+f"(c[3])
        : "r"(a[0]), "r"(a[1]), "r"(a[2]), "r"(a[3]), "r"(b[0]), "r"(b[1]));
}

// ---------------- proj via tensor cores (R11 verbatim) ---------------------
#define PROJ_SMEM (3 * 16384)
__global__ void __launch_bounds__(128) proj_mma(const float* __restrict__ b_enc,
                                                const float* __restrict__ b_pred) {
    extern __shared__ char ds[];
    const uint32_t sbase = smem_u32(ds);
    const int tid  = threadIdx.x;
    const int warp = tid >> 5;
    const int lane = tid & 31;
    const int g = lane >> 2;
    const int t = lane & 3;
    const int wm = (warp >> 1) * 32;
    const int wn = (warp & 1) * 32;

    const __half *Asrc, *Bsrc;
    const float* bias;
    float* dst;
    int m0, n0, K, ktiles;
    const int bx = blockIdx.x;
    if (bx < 160) {
        m0 = (bx / 10) * 64; n0 = (bx % 10) * 64;
        K = DENC; ktiles = 8;
        Asrc = g_encH; Bsrc = g_WeH; bias = b_enc; dst = g_encP;
    } else {
        int bb = bx - 160;
        m0 = (bb / 10) * 64; n0 = (bb % 10) * 64;
        K = DPRED; ktiles = 10;
        Asrc = g_predH; Bsrc = g_WpH; bias = b_pred; dst = g_predP;
    }

    auto load_stage = [&](int s, int kt) {
        const uint32_t stA = sbase + s * 16384;
        const uint32_t stB = stA + 8192;
        const int koff = kt * 64;
#pragma unroll
        for (int q = 0; q < 4; q++) {
            int id = tid + 128 * q;
            int row = id >> 3, c16 = id & 7;
            cp16(stA + swz(row * 128 + c16 * 16), Asrc + (size_t)(m0 + row) * K + koff + c16 * 8);
        }
#pragma unroll
        for (int q = 0; q < 4; q++) {
            int id = tid + 128 * q;
            int row = id >> 3, c16 = id & 7;
            cp16(stB + swz(row * 128 + c16 * 16), Bsrc + (size_t)(n0 + row) * K + koff + c16 * 8);
        }
        asm volatile("cp.async.commit_group;" ::: "memory");
    };

    const int rowA  = wm + (lane & 15);
    const uint32_t kbA  = (lane >> 4) * 16;
    const uint32_t xorA = (uint32_t)(rowA & 7) * 16;
    const int rowB  = wn + (lane & 7) + ((lane >> 4) << 3);
    const uint32_t kbB  = ((lane >> 3) & 1) * 16;
    const uint32_t xorB = (uint32_t)(lane & 7) * 16;

    float acc[2][4][4];
#pragma unroll
    for (int i = 0; i < 2; i++)
#pragma unroll
        for (int j = 0; j < 4; j++)
#pragma unroll
            for (int q = 0; q < 4; q++) acc[i][j][q] = 0.0f;

    auto compute = [&](int s) {
        const uint32_t stA = sbase + s * 16384;
        const uint32_t stB = stA + 8192;
#pragma unroll
        for (int ks = 0; ks < 4; ks++) {
            const uint32_t kb = ks * 32;
            uint32_t a[2][4];
#pragma unroll
            for (int i = 0; i < 2; i++)
                ldsm4(a[i][0], a[i][1], a[i][2], a[i][3],
                      stA + (uint32_t)(rowA + i * 16) * 128 + ((kb + kbA) ^ xorA));
            uint32_t b[4][2];
#pragma unroll
            for (int jp = 0; jp < 2; jp++) {
                uint32_t r0, r1, r2, r3;
                ldsm4(r0, r1, r2, r3,
                      stB + (uint32_t)(rowB + jp * 16) * 128 + ((kb + kbB) ^ xorB));
                b[2*jp][0] = r0; b[2*jp][1] = r1;
                b[2*jp+1][0] = r2; b[2*jp+1][1] = r3;
            }
#pragma unroll
            for (int i = 0; i < 2; i++)
#pragma unroll
                for (int j = 0; j < 4; j++)
                    mma16816(acc[i][j], a[i], b[j]);
        }
    };

    load_stage(0, 0);
    load_stage(1, 1);
#pragma unroll 1
    for (int kt = 0; kt < ktiles; kt++) {
        asm volatile("cp.async.wait_group 1;" ::: "memory");
        __syncthreads();
        if (kt + 2 < ktiles) load_stage((kt + 2) % 3, kt + 2);
        else asm volatile("cp.async.commit_group;" ::: "memory");
        compute(kt % 3);
    }

#pragma unroll
    for (int j = 0; j < 4; j++) {
        int col = n0 + wn + j * 8 + 2 * t;
        float bo0 = __ldg(bias + col), bo1 = __ldg(bias + col + 1);
#pragma unroll
        for (int i = 0; i < 2; i++) {
            int r0 = m0 + wm + i * 16 + g;
            float2 v0, v1;
            v0.x = acc[i][j][0] + bo0; v0.y = acc[i][j][1] + bo1;
            v1.x = acc[i][j][2] + bo0; v1.y = acc[i][j][3] + bo1;
            *(float2*)(dst + (size_t)r0 * DJ + col)       = v0;
            *(float2*)(dst + (size_t)(r0 + 8) * DJ + col) = v1;
        }
    }
}

// ---------------- joint = tanh(encP + predP) -> fp16 ----------------------
// blocks [0,64): W_out^T tiled transpose (runs in tanh's shadow; only the
// gemm consumes g_Wh). blocks [64, 20544): flat tanh (R11 form).
__global__ void __launch_bounds__(256) joint_tanh_kernel(const float* __restrict__ W_out) {
    __shared__ float s[32][33];
    if (blockIdx.x < 64) {               // W_out: 640x1024 -> 640 tiles, 10/block
#pragma unroll
        for (int q = 0; q < 10; q++)
            transpose_tile(W_out, g_Wh, DJ, DV, blockIdx.x * 10 + q, s);
        return;
    }
    int idx = (blockIdx.x - 64) * 256 + threadIdx.x;
    int m  = idx / 80;
    int kq = (idx - m * 80) * 8;
    int bt = m >> 6;
    int u  = m & 63;
    int b  = bt >> 8;
    const float4* e = (const float4*)(g_encP  + (size_t)bt * DJ + kq);
    const float4* p = (const float4*)(g_predP + (size_t)(b * DU + u) * DJ + kq);
    float4 e0 = e[0], e1 = e[1];
    float4 p0 = p[0], p1 = p[1];
    __half2 q0 = __floats2half2_rn(tanha(e0.x + p0.x), tanha(e0.y + p0.y));
    __half2 q1 = __floats2half2_rn(tanha(e0.z + p0.z), tanha(e0.w + p0.w));
    __half2 q2 = __floats2half2_rn(tanha(e1.x + p1.x), tanha(e1.y + p1.y));
    __half2 q3 = __floats2half2_rn(tanha(e1.z + p1.z), tanha(e1.w + p1.w));
    int4 v;
    v.x = *(int*)&q0; v.y = *(int*)&q1; v.z = *(int*)&q2; v.w = *(int*)&q3;
    *(int4*)(g_joint + (size_t)m * DJ + kq) = v;
}

// ==================== main GEMM (R11 verbatim: at HMMA dispatch floor) =====
#define BM 128
#define BN 128
#define BK 64
#define KTILES 10
#define ASZ (BM*BK*2)
#define BSZ (BN*BK*2)
#define STG (ASZ+BSZ)
#define STAGES 3
#define DYN_SMEM (STAGES*STG)

__global__ void __launch_bounds__(256, 2) gemm_lm(const float* __restrict__ b_out,
                                                  float* __restrict__ out) {
    extern __shared__ char ds[];
    const uint32_t sbase = smem_u32(ds);
    const int tid  = threadIdx.x;
    const int warp = tid >> 5;
    const int lane = tid & 31;
    const int g = lane >> 2;
    const int t = lane & 3;
    const int wm = (warp >> 2) * 64;
    const int wn = (warp & 3) * 32;
    const int m0 = blockIdx.y * BM;
    const int n0 = blockIdx.x * BN;

    const __half* aG = g_joint + (size_t)m0 * DJ;
    const __half* bG = g_Wh    + (size_t)n0 * DJ;

    auto load_stage = [&](int s, int kt) {
        const uint32_t stA = sbase + s * STG;
        const uint32_t stB = stA + ASZ;
        const int koff = kt * BK;
#pragma unroll
        for (int q = 0; q < 4; q++) {
            int id = tid + 256 * q;
            int row = id >> 3, c = id & 7;
            cp16(stA + swz(row * 128 + c * 16), aG + (size_t)row * DJ + koff + c * 8);
        }
#pragma unroll
        for (int q = 0; q < 4; q++) {
            int id = tid + 256 * q;
            int row = id >> 3, c = id & 7;
            cp16(stB + swz(row * 128 + c * 16), bG + (size_t)row * DJ + koff + c * 8);
        }
        asm volatile("cp.async.commit_group;" ::: "memory");
    };

    const int rowA  = wm + (lane & 15);
    const uint32_t kbA  = (lane >> 4) * 16;
    const uint32_t xorA = (uint32_t)(rowA & 7) * 16;
    const int rowB  = wn + (lane & 7) + ((lane >> 4) << 3);
    const uint32_t kbB  = ((lane >> 3) & 1) * 16;
    const uint32_t xorB = (uint32_t)(lane & 7) * 16;

    float acc[4][4][4];
#pragma unroll
    for (int i = 0; i < 4; i++)
#pragma unroll
        for (int j = 0; j < 4; j++)
#pragma unroll
            for (int q = 0; q < 4; q++) acc[i][j][q] = 0.0f;

    auto compute = [&](int s) {
        const uint32_t stA = sbase + s * STG;
        const uint32_t stB = stA + ASZ;
#pragma unroll
        for (int ks = 0; ks < 4; ks++) {
            const uint32_t kb = ks * 32;
            uint32_t a[4][4];
#pragma unroll
            for (int i = 0; i < 4; i++)
                ldsm4(a[i][0], a[i][1], a[i][2], a[i][3],
                      stA + (uint32_t)(rowA + i * 16) * 128 + ((kb + kbA) ^ xorA));
            uint32_t b[4][2];
#pragma unroll
            for (int jp = 0; jp < 2; jp++) {
                uint32_t r0, r1, r2, r3;
                ldsm4(r0, r1, r2, r3,
                      stB + (uint32_t)(rowB + jp * 16) * 128 + ((kb + kbB) ^ xorB));
                b[2*jp][0] = r0; b[2*jp][1] = r1;
                b[2*jp+1][0] = r2; b[2*jp+1][1] = r3;
            }
#pragma unroll
            for (int i = 0; i < 4; i++)
#pragma unroll
                for (int j = 0; j < 4; j++)
                    mma16816(acc[i][j], a[i], b[j]);
        }
    };

    load_stage(0, 0);
    load_stage(1, 1);
#pragma unroll 1
    for (int kt = 0; kt < KTILES; kt++) {
        asm volatile("cp.async.wait_group 1;" ::: "memory");
        __syncthreads();
        if (kt + 2 < KTILES) load_stage((kt + 2) % 3, kt + 2);
        else asm volatile("cp.async.commit_group;" ::: "memory");
        compute(kt % 3);
    }

#pragma unroll
    for (int j = 0; j < 4; j++) {
        int col = n0 + wn + j * 8 + 2 * t;
        float bo0 = __ldg(b_out + col), bo1 = __ldg(b_out + col + 1);
#pragma unroll
        for (int i = 0; i < 4; i++) {
            int r0 = m0 + wm + i * 16 + g;
            float2 v0, v1;
            v0.x = fminf(fmaxf(acc[i][j][0] + bo0, -15.0f), 15.0f);
            v0.y = fminf(fmaxf(acc[i][j][1] + bo1, -15.0f), 15.0f);
            v1.x = fminf(fmaxf(acc[i][j][2] + bo0, -15.0f), 15.0f);
            v1.y = fminf(fmaxf(acc[i][j][3] + bo1, -15.0f), 15.0f);
            *(float2*)(out + (size_t)r0 * DV + col)       = v0;
            *(float2*)(out + (size_t)(r0 + 8) * DV + col) = v1;
        }
    }
}

// ---------------- launch ---------------------------------------------------
extern "C" void kernel_launch(void* const* d_in, const int* in_sizes, int n_in,
                              void* d_out, int out_size) {
    const float* enc    = (const float*)d_in[0];
    const float* pred   = (const float*)d_in[1];
    const float* W_enc  = (const float*)d_in[2];
    const float* b_enc  = (const float*)d_in[3];
    const float* W_pred = (const float*)d_in[4];
    const float* b_pred = (const float*)d_in[5];
    const float* W_out  = (const float*)d_in[6];
    const float* b_out  = (const float*)d_in[7];
    float* out = (float*)d_out;

    cudaFuncSetAttribute(gemm_lm, cudaFuncAttributeMaxDynamicSharedMemorySize, DYN_SMEM);
    cudaFuncSetAttribute(proj_mma, cudaFuncAttributeMaxDynamicSharedMemorySize, PROJ_SMEM);

    convert_kernel<<<260, 256>>>(enc, pred, W_enc, W_pred);
    proj_mma<<<200, 128, PROJ_SMEM>>>(b_enc, b_pred);
    joint_tanh_kernel<<<(M_TOTAL * 80) / 256 + 64, 256>>>(W_out);
    gemm_lm<<<dim3(DV / BN, M_TOTAL / BM), 256, DYN_SMEM>>>(b_out, out);
}

// round 15
// speedup vs baseline: 1.1146x; 1.0195x over previous
#include <cuda_runtime.h>
#include <cuda_fp16.h>
#include <cstdint>

#define DB 4
#define DT 256
#define DU 64
#define DENC 512
#define DPRED 640
#define DJ 640
#define DV 1024
#define BT (DB*DT)        // 1024 enc rows
#define BUROWS (DB*DU)    // 256 pred rows
#define M_TOTAL (BT*DU)   // 65536 joint rows

// ---------------- device scratch (no allocations allowed) ----------------
__device__ float  g_encP[BT * DJ];
__device__ float  g_predP[BUROWS * DJ];
__device__ __half g_joint[(size_t)M_TOTAL * DJ];   // 84 MB
__device__ __half g_Wh[DV * DJ];                   // W_out^T [v][k]
__device__ __half g_encH[BT * DENC];
__device__ __half g_predH[BUROWS * DPRED];
__device__ __half g_WeH[DJ * DENC];                // W_enc^T [j][k]
__device__ __half g_WpH[DJ * DPRED];               // W_pred^T [j][k]

// ---------------- tanh via MUFU.TANH --------------------------------------
__device__ __forceinline__ float tanha(float x) {
    float y;
    asm("tanh.approx.f32 %0, %1;" : "=f"(y) : "f"(x));
    return y;
}

// ---------------- tiled fp32->fp16 transpose (coalesced both ways) -------
__device__ __forceinline__ void transpose_tile(const float* __restrict__ src,
                                               __half* __restrict__ dst,
                                               int K, int J, int tile_idx,
                                               float (*s)[33]) {
    const int tpr = J >> 5;
    const int tk = tile_idx / tpr;
    const int tj = tile_idx - tk * tpr;
    const int k0 = tk * 32, j0 = tj * 32;
    const int tx = threadIdx.x & 31, ty = threadIdx.x >> 5;
#pragma unroll
    for (int r = ty; r < 32; r += 8)
        s[r][tx] = src[(size_t)(k0 + r) * J + j0 + tx];
    __syncthreads();
#pragma unroll
    for (int r = ty; r < 32; r += 8)
        dst[(size_t)(j0 + r) * K + k0 + tx] = __float2half_rn(s[tx][r]);
    __syncthreads();
}

// ---------------- convert: enc/pred fp16 + W_enc/W_pred tiled transpose ---
__global__ void __launch_bounds__(256) convert_kernel(const float* __restrict__ enc,
                                                      const float* __restrict__ pred,
                                                      const float* __restrict__ W_enc,
                                                      const float* __restrict__ W_pred) {
    __shared__ float s[32][33];
    const int bx = blockIdx.x, tid = threadIdx.x;
    if (bx < 64) {
        const float4* src = (const float4*)enc;
        for (int i = bx * 256 + tid; i < (BT * DENC) / 4; i += 64 * 256) {
            float4 v = src[i];
            __half2 h0 = __floats2half2_rn(v.x, v.y);
            __half2 h1 = __floats2half2_rn(v.z, v.w);
            int2 o; o.x = *(int*)&h0; o.y = *(int*)&h1;
            ((int2*)g_encH)[i] = o;
        }
    } else if (bx < 80) {
        const float4* src = (const float4*)pred;
        for (int i = (bx - 64) * 256 + tid; i < (BUROWS * DPRED) / 4; i += 16 * 256) {
            float4 v = src[i];
            __half2 h0 = __floats2half2_rn(v.x, v.y);
            __half2 h1 = __floats2half2_rn(v.z, v.w);
            int2 o; o.x = *(int*)&h0; o.y = *(int*)&h1;
            ((int2*)g_predH)[i] = o;
        }
    } else if (bx < 160) {
#pragma unroll
        for (int q = 0; q < 4; q++)
            transpose_tile(W_enc, g_WeH, DENC, DJ, (bx - 80) * 4 + q, s);
    } else {
#pragma unroll
        for (int q = 0; q < 4; q++)
            transpose_tile(W_pred, g_WpH, DPRED, DJ, (bx - 160) * 4 + q, s);
    }
}

// ---------------- shared GEMM helpers --------------------------------------
__device__ __forceinline__ uint32_t smem_u32(const void* p) {
    uint32_t a;
    asm("{ .reg .u64 t; cvta.to.shared.u64 t, %1; cvt.u32.u64 %0, t; }" : "=r"(a) : "l"(p));
    return a;
}
__device__ __forceinline__ uint32_t swz(uint32_t o) { return o ^ ((o >> 3) & 0x70); }
__device__ __forceinline__ void cp16(uint32_t dst, const void* src) {
    asm volatile("cp.async.cg.shared.global [%0], [%1], 16;" :: "r"(dst), "l"(src));
}
__device__ __forceinline__ void ldsm4(uint32_t& r0, uint32_t& r1, uint32_t& r2,
                                      uint32_t& r3, uint32_t a) {
    asm volatile("ldmatrix.sync.aligned.m8n8.x4.shared.b16 {%0,%1,%2,%3}, [%4];"
                 : "=r"(r0), "=r"(r1), "=r"(r2), "=r"(r3) : "r"(a));
}
__device__ __forceinline__ void mma16816(float c[4], const uint32_t a[4], const uint32_t b[2]) {
    asm volatile(
        "mma.sync.aligned.m16n8k16.row.col.f32.f16.f16.f32 "
        "{%0,%1,%2,%3}, {%4,%5,%6,%7}, {%8,%9}, {%0,%1,%2,%3};\n"
        : "+f"(c[0]), "+f"(c[1]), "+f"(c[2]), "+f"(c[3])
        : "r"(a[0]), "r"(a[1]), "r"(a[2]), "r"(a[3]), "r"(b[0]), "r"(b[1]));
}

// ---------------- proj via tensor cores (R11 verbatim) ---------------------
#define PROJ_SMEM (3 * 16384)
__global__ void __launch_bounds__(128) proj_mma(const float* __restrict__ b_enc,
                                                const float* __restrict__ b_pred) {
    extern __shared__ char ds[];
    const uint32_t sbase = smem_u32(ds);
    const int tid  = threadIdx.x;
    const int warp = tid >> 5;
    const int lane = tid & 31;
    const int g = lane >> 2;
    const int t = lane & 3;
    const int wm = (warp >> 1) * 32;
    const int wn = (warp & 1) * 32;

    const __half *Asrc, *Bsrc;
    const float* bias;
    float* dst;
    int m0, n0, K, ktiles;
    const int bx = blockIdx.x;
    if (bx < 160) {
        m0 = (bx / 10) * 64; n0 = (bx % 10) * 64;
        K = DENC; ktiles = 8;
        Asrc = g_encH; Bsrc = g_WeH; bias = b_enc; dst = g_encP;
    } else {
        int bb = bx - 160;
        m0 = (bb / 10) * 64; n0 = (bb % 10) * 64;
        K = DPRED; ktiles = 10;
        Asrc = g_predH; Bsrc = g_WpH; bias = b_pred; dst = g_predP;
    }

    auto load_stage = [&](int s, int kt) {
        const uint32_t stA = sbase + s * 16384;
        const uint32_t stB = stA + 8192;
        const int koff = kt * 64;
#pragma unroll
        for (int q = 0; q < 4; q++) {
            int id = tid + 128 * q;
            int row = id >> 3, c16 = id & 7;
            cp16(stA + swz(row * 128 + c16 * 16), Asrc + (size_t)(m0 + row) * K + koff + c16 * 8);
        }
#pragma unroll
        for (int q = 0; q < 4; q++) {
            int id = tid + 128 * q;
            int row = id >> 3, c16 = id & 7;
            cp16(stB + swz(row * 128 + c16 * 16), Bsrc + (size_t)(n0 + row) * K + koff + c16 * 8);
        }
        asm volatile("cp.async.commit_group;" ::: "memory");
    };

    const int rowA  = wm + (lane & 15);
    const uint32_t kbA  = (lane >> 4) * 16;
    const uint32_t xorA = (uint32_t)(rowA & 7) * 16;
    const int rowB  = wn + (lane & 7) + ((lane >> 4) << 3);
    const uint32_t kbB  = ((lane >> 3) & 1) * 16;
    const uint32_t xorB = (uint32_t)(lane & 7) * 16;

    float acc[2][4][4];
#pragma unroll
    for (int i = 0; i < 2; i++)
#pragma unroll
        for (int j = 0; j < 4; j++)
#pragma unroll
            for (int q = 0; q < 4; q++) acc[i][j][q] = 0.0f;

    auto compute = [&](int s) {
        const uint32_t stA = sbase + s * 16384;
        const uint32_t stB = stA + 8192;
#pragma unroll
        for (int ks = 0; ks < 4; ks++) {
            const uint32_t kb = ks * 32;
            uint32_t a[2][4];
#pragma unroll
            for (int i = 0; i < 2; i++)
                ldsm4(a[i][0], a[i][1], a[i][2], a[i][3],
                      stA + (uint32_t)(rowA + i * 16) * 128 + ((kb + kbA) ^ xorA));
            uint32_t b[4][2];
#pragma unroll
            for (int jp = 0; jp < 2; jp++) {
                uint32_t r0, r1, r2, r3;
                ldsm4(r0, r1, r2, r3,
                      stB + (uint32_t)(rowB + jp * 16) * 128 + ((kb + kbB) ^ xorB));
                b[2*jp][0] = r0; b[2*jp][1] = r1;
                b[2*jp+1][0] = r2; b[2*jp+1][1] = r3;
            }
#pragma unroll
            for (int i = 0; i < 2; i++)
#pragma unroll
                for (int j = 0; j < 4; j++)
                    mma16816(acc[i][j], a[i], b[j]);
        }
    };

    load_stage(0, 0);
    load_stage(1, 1);
#pragma unroll 1
    for (int kt = 0; kt < ktiles; kt++) {
        asm volatile("cp.async.wait_group 1;" ::: "memory");
        __syncthreads();
        if (kt + 2 < ktiles) load_stage((kt + 2) % 3, kt + 2);
        else asm volatile("cp.async.commit_group;" ::: "memory");
        compute(kt % 3);
    }

#pragma unroll
    for (int j = 0; j < 4; j++) {
        int col = n0 + wn + j * 8 + 2 * t;
        float bo0 = __ldg(bias + col), bo1 = __ldg(bias + col + 1);
#pragma unroll
        for (int i = 0; i < 2; i++) {
            int r0 = m0 + wm + i * 16 + g;
            float2 v0, v1;
            v0.x = acc[i][j][0] + bo0; v0.y = acc[i][j][1] + bo1;
            v1.x = acc[i][j][2] + bo0; v1.y = acc[i][j][3] + bo1;
            *(float2*)(dst + (size_t)r0 * DJ + col)       = v0;
            *(float2*)(dst + (size_t)(r0 + 8) * DJ + col) = v1;
        }
    }
}

// ---------------- joint = tanh(encP + predP) -> fp16, register-tiled -----
// blocks [0,64): W_out^T transpose (gemm-only input, runs in tanh's shadow).
// Rest: each thread covers a 2(bt) x 4(u) row-group at one 8-wide k-chunk:
// enc chunks read once per 4 u's, pred chunks once per 2 bt's (L2 336->126MB).
__global__ void __launch_bounds__(256) joint_tanh_kernel(const float* __restrict__ W_out) {
    __shared__ float s[32][33];
    if (blockIdx.x < 64) {               // W_out: 640x1024 -> 640 tiles, 10/block
#pragma unroll
        for (int q = 0; q < 10; q++)
            transpose_tile(W_out, g_Wh, DJ, DV, blockIdx.x * 10 + q, s);
        return;
    }
    const int idx = (blockIdx.x - 64) * 256 + threadIdx.x;   // 655360 items
    const int grp = idx / 80;            // 8192 groups of 8 rows
    const int ch  = idx - grp * 80;      // k-chunk (8 floats)
    const int bt0 = (grp >> 4) * 2;
    const int u0  = (grp & 15) * 4;
    const int b   = bt0 >> 8;

    float4 e[2][2];
#pragma unroll
    for (int i = 0; i < 2; i++) {
        const float4* ep = (const float4*)(g_encP + (size_t)(bt0 + i) * DJ + ch * 8);
        e[i][0] = ep[0]; e[i][1] = ep[1];
    }
    float4 p[4][2];
#pragma unroll
    for (int j = 0; j < 4; j++) {
        const float4* pp = (const float4*)(g_predP + (size_t)(b * DU + u0 + j) * DJ + ch * 8);
        p[j][0] = pp[0]; p[j][1] = pp[1];
    }
#pragma unroll
    for (int i = 0; i < 2; i++) {
#pragma unroll
        for (int j = 0; j < 4; j++) {
            __half2 q0 = __floats2half2_rn(tanha(e[i][0].x + p[j][0].x), tanha(e[i][0].y + p[j][0].y));
            __half2 q1 = __floats2half2_rn(tanha(e[i][0].z + p[j][0].z), tanha(e[i][0].w + p[j][0].w));
            __half2 q2 = __floats2half2_rn(tanha(e[i][1].x + p[j][1].x), tanha(e[i][1].y + p[j][1].y));
            __half2 q3 = __floats2half2_rn(tanha(e[i][1].z + p[j][1].z), tanha(e[i][1].w + p[j][1].w));
            int4 v;
            v.x = *(int*)&q0; v.y = *(int*)&q1; v.z = *(int*)&q2; v.w = *(int*)&q3;
            size_t m = (size_t)(bt0 + i) * DU + (u0 + j);
            *(int4*)(g_joint + m * DJ + ch * 8) = v;
        }
    }
}

// ==================== main GEMM (R11 verbatim) =============================
#define BM 128
#define BN 128
#define BK 64
#define KTILES 10
#define ASZ (BM*BK*2)
#define BSZ (BN*BK*2)
#define STG (ASZ+BSZ)
#define STAGES 3
#define DYN_SMEM (STAGES*STG)

__global__ void __launch_bounds__(256, 2) gemm_lm(const float* __restrict__ b_out,
                                                  float* __restrict__ out) {
    extern __shared__ char ds[];
    const uint32_t sbase = smem_u32(ds);
    const int tid  = threadIdx.x;
    const int warp = tid >> 5;
    const int lane = tid & 31;
    const int g = lane >> 2;
    const int t = lane & 3;
    const int wm = (warp >> 2) * 64;
    const int wn = (warp & 3) * 32;
    const int m0 = blockIdx.y * BM;
    const int n0 = blockIdx.x * BN;

    const __half* aG = g_joint + (size_t)m0 * DJ;
    const __half* bG = g_Wh    + (size_t)n0 * DJ;

    auto load_stage = [&](int s, int kt) {
        const uint32_t stA = sbase + s * STG;
        const uint32_t stB = stA + ASZ;
        const int koff = kt * BK;
#pragma unroll
        for (int q = 0; q < 4; q++) {
            int id = tid + 256 * q;
            int row = id >> 3, c = id & 7;
            cp16(stA + swz(row * 128 + c * 16), aG + (size_t)row * DJ + koff + c * 8);
        }
#pragma unroll
        for (int q = 0; q < 4; q++) {
            int id = tid + 256 * q;
            int row = id >> 3, c = id & 7;
            cp16(stB + swz(row * 128 + c * 16), bG + (size_t)row * DJ + koff + c * 8);
        }
        asm volatile("cp.async.commit_group;" ::: "memory");
    };

    const int rowA  = wm + (lane & 15);
    const uint32_t kbA  = (lane >> 4) * 16;
    const uint32_t xorA = (uint32_t)(rowA & 7) * 16;
    const int rowB  = wn + (lane & 7) + ((lane >> 4) << 3);
    const uint32_t kbB  = ((lane >> 3) & 1) * 16;
    const uint32_t xorB = (uint32_t)(lane & 7) * 16;

    float acc[4][4][4];
#pragma unroll
    for (int i = 0; i < 4; i++)
#pragma unroll
        for (int j = 0; j < 4; j++)
#pragma unroll
            for (int q = 0; q < 4; q++) acc[i][j][q] = 0.0f;

    auto compute = [&](int s) {
        const uint32_t stA = sbase + s * STG;
        const uint32_t stB = stA + ASZ;
#pragma unroll
        for (int ks = 0; ks < 4; ks++) {
            const uint32_t kb = ks * 32;
            uint32_t a[4][4];
#pragma unroll
            for (int i = 0; i < 4; i++)
                ldsm4(a[i][0], a[i][1], a[i][2], a[i][3],
                      stA + (uint32_t)(rowA + i * 16) * 128 + ((kb + kbA) ^ xorA));
            uint32_t b[4][2];
#pragma unroll
            for (int jp = 0; jp < 2; jp++) {
                uint32_t r0, r1, r2, r3;
                ldsm4(r0, r1, r2, r3,
                      stB + (uint32_t)(rowB + jp * 16) * 128 + ((kb + kbB) ^ xorB));
                b[2*jp][0] = r0; b[2*jp][1] = r1;
                b[2*jp+1][0] = r2; b[2*jp+1][1] = r3;
            }
#pragma unroll
            for (int i = 0; i < 4; i++)
#pragma unroll
                for (int j = 0; j < 4; j++)
                    mma16816(acc[i][j], a[i], b[j]);
        }
    };

    load_stage(0, 0);
    load_stage(1, 1);
#pragma unroll 1
    for (int kt = 0; kt < KTILES; kt++) {
        asm volatile("cp.async.wait_group 1;" ::: "memory");
        __syncthreads();
        if (kt + 2 < KTILES) load_stage((kt + 2) % 3, kt + 2);
        else asm volatile("cp.async.commit_group;" ::: "memory");
        compute(kt % 3);
    }

#pragma unroll
    for (int j = 0; j < 4; j++) {
        int col = n0 + wn + j * 8 + 2 * t;
        float bo0 = __ldg(b_out + col), bo1 = __ldg(b_out + col + 1);
#pragma unroll
        for (int i = 0; i < 4; i++) {
            int r0 = m0 + wm + i * 16 + g;
            float2 v0, v1;
            v0.x = fminf(fmaxf(acc[i][j][0] + bo0, -15.0f), 15.0f);
            v0.y = fminf(fmaxf(acc[i][j][1] + bo1, -15.0f), 15.0f);
            v1.x = fminf(fmaxf(acc[i][j][2] + bo0, -15.0f), 15.0f);
            v1.y = fminf(fmaxf(acc[i][j][3] + bo1, -15.0f), 15.0f);
            *(float2*)(out + (size_t)r0 * DV + col)       = v0;
            *(float2*)(out + (size_t)(r0 + 8) * DV + col) = v1;
        }
    }
}

// ---------------- launch ---------------------------------------------------
extern "C" void kernel_launch(void* const* d_in, const int* in_sizes, int n_in,
                              void* d_out, int out_size) {
    const float* enc    = (const float*)d_in[0];
    const float* pred   = (const float*)d_in[1];
    const float* W_enc  = (const float*)d_in[2];
    const float* b_enc  = (const float*)d_in[3];
    const float* W_pred = (const float*)d_in[4];
    const float* b_pred = (const float*)d_in[5];
    const float* W_out  = (const float*)d_in[6];
    const float* b_out  = (const float*)d_in[7];
    float* out = (float*)d_out;

    cudaFuncSetAttribute(gemm_lm, cudaFuncAttributeMaxDynamicSharedMemorySize, DYN_SMEM);
    cudaFuncSetAttribute(proj_mma, cudaFuncAttributeMaxDynamicSharedMemorySize, PROJ_SMEM);

    convert_kernel<<<260, 256>>>(enc, pred, W_enc, W_pred);
    proj_mma<<<200, 128, PROJ_SMEM>>>(b_enc, b_pred);
    joint_tanh_kernel<<<(M_TOTAL * 80) / (256 * 8) + 64, 256>>>(W_out);
    gemm_lm<<<dim3(DV / BN, M_TOTAL / BM), 256, DYN_SMEM>>>(b_out, out);
}